// round 10
// baseline (speedup 1.0000x reference)
#include <cuda_runtime.h>
#include <math.h>
#include <stdint.h>

// Problem constants
#define BB 8192
#define KK 8
#define SS 4
#define DD 512
#define MW (BB * SS)                     // 32768 rows of workspace-space
#define SCALE_F 0.044194173824159216f    // 512^-0.5
#define LN_EPS 1e-5f
#define NEG_INF (__int_as_float(0xff800000))

// ---------------------------------------------------------------------------
// Scratch (device globals). NEVER passed as host-side kernel arguments —
// device code resolves them via selectors (host shadow symbols on GB300 ATS
// silently alias host memory).
// ---------------------------------------------------------------------------
__device__ float g_bufA[(size_t)MW * DD];        // mhat, then z
__device__ float g_bufB[(size_t)MW * DD];        // vmix (raw, pre-LN)
__device__ float g_bufK[(size_t)MW * DD];        // wsup (projected wsu)
__device__ float g_Aw[SS * DD];                  // Wk_w^T Qws   [S,D]
__device__ float g_M[DD * DD];                   // Wq_r^T Wk_r  [D,D]
__device__ float g_Wov[DD * DD];                 // Wo Wv_r      [D,D]
__device__ float g_part[4 * MW * 2];             // LN partials (sum,sumsq)
__device__ float g_mu[MW];                       // LN mean per wsu row
__device__ float g_rs[MW];                       // LN rsqrt(var+eps) per row

// ---------------------------------------------------------------------------
// Helpers
// ---------------------------------------------------------------------------
__device__ __forceinline__ float warp_sum(float v) {
    #pragma unroll
    for (int o = 16; o; o >>= 1) v += __shfl_xor_sync(0xffffffffu, v, o);
    return v;
}

__device__ __forceinline__ float warp_dot512(const float* __restrict__ a,
                                             const float* __restrict__ b) {
    int lane = threadIdx.x & 31;
    const float4* a4 = reinterpret_cast<const float4*>(a);
    const float4* b4 = reinterpret_cast<const float4*>(b);
    float s = 0.f;
    #pragma unroll
    for (int i = 0; i < 4; i++) {
        float4 x = a4[lane + i * 32];
        float4 y = b4[lane + i * 32];
        s = fmaf(x.x, y.x, s);
        s = fmaf(x.y, y.y, s);
        s = fmaf(x.z, y.z, s);
        s = fmaf(x.w, y.w, s);
    }
    return warp_sum(s);
}

__device__ __forceinline__ uint32_t f2tf32(float f) {
    uint32_t r;
    asm("cvt.rna.tf32.f32 %0, %1;" : "=r"(r) : "f"(f));
    return r;
}

__device__ __forceinline__ void mma_tf32(float* c, const uint32_t* a,
                                         const uint32_t* b) {
    asm volatile(
        "mma.sync.aligned.m16n8k8.row.col.f32.tf32.tf32.f32 "
        "{%0,%1,%2,%3}, {%4,%5,%6,%7}, {%8,%9}, {%0,%1,%2,%3};\n"
        : "+f"(c[0]), "+f"(c[1]), "+f"(c[2]), "+f"(c[3])
        : "r"(a[0]), "r"(a[1]), "r"(a[2]), "r"(a[3]), "r"(b[0]), "r"(b[1]));
}

// ---------------------------------------------------------------------------
// Precompute Aw[s,d] = sum_e Qws[s,e]*Wk_w[e,d], Qws = ws @ Wq_w^T
// ---------------------------------------------------------------------------
__global__ __launch_bounds__(512) void aw_kernel(
    const float* __restrict__ ws, const float* __restrict__ Wq_w,
    const float* __restrict__ Wk_w) {
    const int s = blockIdx.x;
    const int tid = threadIdx.x;
    const int warp = tid >> 5;
    __shared__ float qs[DD];

    for (int e = warp; e < DD; e += 16) {
        float d = warp_dot512(ws + s * DD, Wq_w + (size_t)e * DD);
        if ((tid & 31) == 0) qs[e] = d;
    }
    __syncthreads();

    float acc = 0.f;
    for (int e = 0; e < DD; e++)
        acc = fmaf(qs[e], Wk_w[(size_t)e * DD + tid], acc);
    g_Aw[s * DD + tid] = acc;
}

// ---------------------------------------------------------------------------
// Small 512^3 GEMM (fp32, exact): C = opA(A)*B. c_sel: 0->g_M, 1->g_Wov.
// ---------------------------------------------------------------------------
template <int TRANSA>
__global__ __launch_bounds__(256) void small_gemm(
    const float* __restrict__ A, const float* __restrict__ B, int c_sel) {
    float* C = (c_sel == 0) ? g_M : g_Wov;
    __shared__ float As[32][33];
    __shared__ float Bs[32][33];
    const int m0 = blockIdx.y * 32;
    const int n0 = blockIdx.x * 32;
    const int tid = threadIdx.x;
    const int tr = tid >> 4;
    const int tc = tid & 15;

    float c00 = 0.f, c01 = 0.f, c10 = 0.f, c11 = 0.f;

    for (int e0 = 0; e0 < DD; e0 += 32) {
        #pragma unroll
        for (int i = tid; i < 1024; i += 256) {
            if (TRANSA) {
                int e = i >> 5, m = i & 31;
                As[e][m] = A[(size_t)(e0 + e) * DD + m0 + m];
            } else {
                int m = i >> 5, e = i & 31;
                As[e][m] = A[(size_t)(m0 + m) * DD + e0 + e];
            }
        }
        #pragma unroll
        for (int i = tid; i < 1024; i += 256) {
            int e = i >> 5, n = i & 31;
            Bs[e][n] = B[(size_t)(e0 + e) * DD + n0 + n];
        }
        __syncthreads();
        #pragma unroll
        for (int e = 0; e < 32; e++) {
            float a0 = As[e][tr * 2], a1 = As[e][tr * 2 + 1];
            float b0 = Bs[e][tc * 2], b1 = Bs[e][tc * 2 + 1];
            c00 = fmaf(a0, b0, c00);
            c01 = fmaf(a0, b1, c01);
            c10 = fmaf(a1, b0, c10);
            c11 = fmaf(a1, b1, c11);
        }
        __syncthreads();
    }
    C[(size_t)(m0 + tr * 2) * DD + n0 + tc * 2] = c00;
    C[(size_t)(m0 + tr * 2) * DD + n0 + tc * 2 + 1] = c01;
    C[(size_t)(m0 + tr * 2 + 1) * DD + n0 + tc * 2] = c10;
    C[(size_t)(m0 + tr * 2 + 1) * DD + n0 + tc * 2 + 1] = c11;
}

// ---------------------------------------------------------------------------
// tf32 tensor-core GEMM (NT) with fused LN machinery.
//   mode 1 (vmix GEMM): plain compute, epilogue accumulates per-row partial
//          sum/sumsq of (ws + C) into g_part.
//   mode 2 (z|wsup GEMM): A-tile commit applies LN: (ws+A-mu)*rs*gam+bet.
// Selection in device code:
//   a_sel: 0=g_bufA 1=g_bufB
//   wmode: 0=Wext(N=512)  1=cols[0,512)->g_M, [512,1024)->g_Wov
//   cmode: 0=g_bufB        1=cols[0,512)->g_bufA, [512,1024)->g_bufK
// ---------------------------------------------------------------------------
#define TM 128
#define TN 128
#define TK 32

__global__ __launch_bounds__(256) void gemm_tf32(
    const float* __restrict__ Wext, const float* __restrict__ wsp,
    const float* __restrict__ gam, const float* __restrict__ bet,
    int a_sel, int wmode, int cmode, int mode) {
    const float* A = (a_sel == 0) ? g_bufA : g_bufB;
    const int bm = blockIdx.x * TM;
    const int bn = blockIdx.y * TN;

    const float* W;
    int wn0;
    if (wmode == 0) { W = Wext; wn0 = bn; }
    else { W = (bn < 512) ? g_M : g_Wov; wn0 = bn & 511; }

    float* C;
    int cn0;
    if (cmode == 0) { C = g_bufB; cn0 = bn; }
    else { C = (bn < 512) ? g_bufA : g_bufK; cn0 = bn & 511; }

    __shared__ uint32_t As[TM][36];
    __shared__ uint32_t Bs[TN][36];
    __shared__ float sws[SS][DD];    // workspace rows (8 KB)
    __shared__ float rsum[TM];
    __shared__ float rsq[TM];

    const int tid = threadIdx.x;
    const int lane = tid & 31;
    const int warp = tid >> 5;
    const int wm = warp & 1;
    const int wn = warp >> 1;
    const int gid = lane >> 2;
    const int tig = lane & 3;

    // one-time smem preloads
    for (int i = tid; i < SS * DD / 4; i += 256)
        reinterpret_cast<float4*>(&sws[0][0])[i] =
            reinterpret_cast<const float4*>(wsp)[i];
    if (mode == 1 && tid < TM) { rsum[tid] = 0.f; rsq[tid] = 0.f; }

    // per-thread LN row constants (mode 2): rows are fixed per (tid, i)
    float mur[4], rsr[4];
    if (mode == 2) {
        #pragma unroll
        for (int i = 0; i < 4; i++) {
            int r = (tid + i * 256) >> 3;
            mur[i] = g_mu[bm + r];
            rsr[i] = g_rs[bm + r];
        }
    }

    float acc[4][4][4];
    #pragma unroll
    for (int i = 0; i < 4; i++)
        #pragma unroll
        for (int j = 0; j < 4; j++)
            #pragma unroll
            for (int r = 0; r < 4; r++) acc[i][j][r] = 0.f;

    float4 ra[4], rw[4];
    #pragma unroll
    for (int i = 0; i < 4; i++) {
        int idx = tid + i * 256;
        int r = idx >> 3, c = (idx & 7) * 4;
        ra[i] = *reinterpret_cast<const float4*>(A + (size_t)(bm + r) * DD + c);
        rw[i] = *reinterpret_cast<const float4*>(W + (size_t)(wn0 + r) * DD + c);
    }
    __syncthreads();   // sws ready before first commit uses it

    for (int t = 0; t < DD / TK; t++) {
        #pragma unroll
        for (int i = 0; i < 4; i++) {
            int idx = tid + i * 256;
            int r = idx >> 3, c = (idx & 7) * 4;
            if (mode == 2) {
                int s = r & 3;
                int gc = t * TK + c;
                float v[4] = {ra[i].x, ra[i].y, ra[i].z, ra[i].w};
                #pragma unroll
                for (int j = 0; j < 4; j++) {
                    float x = (sws[s][gc + j] + v[j] - mur[i]) * rsr[i];
                    x = fmaf(x, __ldg(&gam[gc + j]), __ldg(&bet[gc + j]));
                    As[r][c + j] = f2tf32(x);
                }
            } else {
                As[r][c + 0] = f2tf32(ra[i].x); As[r][c + 1] = f2tf32(ra[i].y);
                As[r][c + 2] = f2tf32(ra[i].z); As[r][c + 3] = f2tf32(ra[i].w);
            }
            Bs[r][c + 0] = f2tf32(rw[i].x); Bs[r][c + 1] = f2tf32(rw[i].y);
            Bs[r][c + 2] = f2tf32(rw[i].z); Bs[r][c + 3] = f2tf32(rw[i].w);
        }
        __syncthreads();

        if (t + 1 < DD / TK) {
            int k0 = (t + 1) * TK;
            #pragma unroll
            for (int i = 0; i < 4; i++) {
                int idx = tid + i * 256;
                int r = idx >> 3, c = (idx & 7) * 4;
                ra[i] = *reinterpret_cast<const float4*>(
                    A + (size_t)(bm + r) * DD + k0 + c);
                rw[i] = *reinterpret_cast<const float4*>(
                    W + (size_t)(wn0 + r) * DD + k0 + c);
            }
        }

        #pragma unroll
        for (int ks = 0; ks < 4; ks++) {
            uint32_t af[4][4], bf[4][2];
            #pragma unroll
            for (int mt = 0; mt < 4; mt++) {
                int r0 = wm * 64 + mt * 16 + gid;
                af[mt][0] = As[r0][ks * 8 + tig];
                af[mt][1] = As[r0 + 8][ks * 8 + tig];
                af[mt][2] = As[r0][ks * 8 + tig + 4];
                af[mt][3] = As[r0 + 8][ks * 8 + tig + 4];
            }
            #pragma unroll
            for (int nt = 0; nt < 4; nt++) {
                int c0 = wn * 32 + nt * 8 + gid;
                bf[nt][0] = Bs[c0][ks * 8 + tig];
                bf[nt][1] = Bs[c0][ks * 8 + tig + 4];
            }
            #pragma unroll
            for (int mt = 0; mt < 4; mt++)
                #pragma unroll
                for (int nt = 0; nt < 4; nt++)
                    mma_tf32(acc[mt][nt], af[mt], bf[nt]);
        }
        __syncthreads();
    }

    // store C
    #pragma unroll
    for (int mt = 0; mt < 4; mt++) {
        #pragma unroll
        for (int nt = 0; nt < 4; nt++) {
            int grow = bm + wm * 64 + mt * 16 + gid;
            int gcol = cn0 + wn * 32 + nt * 8 + 2 * tig;
            *reinterpret_cast<float2*>(&C[(size_t)grow * DD + gcol]) =
                make_float2(acc[mt][nt][0], acc[mt][nt][1]);
            *reinterpret_cast<float2*>(&C[(size_t)(grow + 8) * DD + gcol]) =
                make_float2(acc[mt][nt][2], acc[mt][nt][3]);
        }
    }

    // mode 1 epilogue: per-row partial LN stats of (ws + vmix)
    if (mode == 1) {
        const int s = gid & 3;          // (bm+row)&3 == row&3 == gid&3
        #pragma unroll
        for (int mt = 0; mt < 4; mt++) {
            int lr0 = wm * 64 + mt * 16 + gid;
            float s0 = 0.f, q0 = 0.f, s1 = 0.f, q1 = 0.f;
            #pragma unroll
            for (int nt = 0; nt < 4; nt++) {
                int col = cn0 + wn * 32 + nt * 8 + 2 * tig;
                float x0 = acc[mt][nt][0] + sws[s][col];
                float x1 = acc[mt][nt][1] + sws[s][col + 1];
                float x2 = acc[mt][nt][2] + sws[s][col];
                float x3 = acc[mt][nt][3] + sws[s][col + 1];
                s0 += x0 + x1; q0 += x0 * x0 + x1 * x1;
                s1 += x2 + x3; q1 += x2 * x2 + x3 * x3;
            }
            atomicAdd(&rsum[lr0], s0);
            atomicAdd(&rsq[lr0], q0);
            atomicAdd(&rsum[lr0 + 8], s1);
            atomicAdd(&rsq[lr0 + 8], q1);
        }
        __syncthreads();
        if (tid < TM) {
            size_t o = ((size_t)(bn >> 7) * MW + bm + tid) * 2;
            g_part[o] = rsum[tid];
            g_part[o + 1] = rsq[tid];
        }
    }
}

// ---------------------------------------------------------------------------
// Finalize LN stats: mu, rsqrt(var+eps) per wsu row.
// ---------------------------------------------------------------------------
__global__ __launch_bounds__(256) void finalize_stats() {
    int r = blockIdx.x * 256 + threadIdx.x;
    float s = 0.f, q = 0.f;
    #pragma unroll
    for (int j = 0; j < 4; j++) {
        size_t o = ((size_t)j * MW + r) * 2;
        s += g_part[o];
        q += g_part[o + 1];
    }
    float mu = s * (1.f / DD);
    float var = q * (1.f / DD) - mu * mu;
    g_mu[r] = mu;
    g_rs[r] = rsqrtf(var + LN_EPS);
}

// ---------------------------------------------------------------------------
// Write attention -> mhat (g_bufA). One block per batch b.
// ---------------------------------------------------------------------------
__global__ __launch_bounds__(256) void write_attn_kernel(
    const float* __restrict__ hidden,
    const int* __restrict__ mask) {
    const int b = blockIdx.x;
    const int tid = threadIdx.x;
    const int warp = tid >> 5;

    __shared__ float sh[KK][DD];
    __shared__ float logits[SS][KK];
    __shared__ float p[SS][KK];
    __shared__ int smask[KK];

    if (tid < KK) smask[tid] = mask[b * KK + tid];

    for (int i = tid; i < KK * (DD / 4); i += 256) {
        int k = i / (DD / 4), c4 = i % (DD / 4);
        reinterpret_cast<float4*>(sh[k])[c4] =
            reinterpret_cast<const float4*>(hidden + (size_t)(b * KK + k) * DD)[c4];
    }
    __syncthreads();

    for (int pr = warp; pr < SS * KK; pr += 8) {
        int s = pr >> 3, k = pr & 7;
        float d = warp_dot512(g_Aw + s * DD, sh[k]) * SCALE_F;
        if ((tid & 31) == 0) logits[s][k] = d;
    }
    __syncthreads();

    if (tid < SS) {
        int s = tid;
        float m = NEG_INF;
        #pragma unroll
        for (int k = 0; k < KK; k++)
            if (smask[k] != 0) m = fmaxf(m, logits[s][k]);
        float pe[KK], sum = 0.f;
        #pragma unroll
        for (int k = 0; k < KK; k++) {
            float e = (smask[k] != 0) ? expf(logits[s][k] - m) : 0.f;
            pe[k] = e; sum += e;
        }
        float inv = (sum > 0.f) ? 1.f / sum : 0.f;
        #pragma unroll
        for (int k = 0; k < KK; k++) p[s][k] = pe[k] * inv;
    }
    __syncthreads();

    #pragma unroll
    for (int s = 0; s < SS; s++) {
        #pragma unroll
        for (int h = 0; h < 2; h++) {
            int d = tid + h * 256;
            float acc = 0.f;
            #pragma unroll
            for (int k = 0; k < KK; k++) acc = fmaf(p[s][k], sh[k][d], acc);
            g_bufA[(size_t)(b * SS + s) * DD + d] = acc;
        }
    }
}

// ---------------------------------------------------------------------------
// Read attention + FINAL LN fused. One block per batch b.
//   logits[k,s] = SCALE * h[b,k] . z[b,s]  (z in g_bufA); softmax over s
//   x[k,:] = h[b,k,:] + sum_s p[k,s]*wsup[b,s,:]; out = LN(x)
// ---------------------------------------------------------------------------
__global__ __launch_bounds__(256) void read_attn_ln_kernel(
    const float* __restrict__ hidden,
    const float* __restrict__ gam, const float* __restrict__ bet,
    float* __restrict__ out) {
    const int b = blockIdx.x;
    const int tid = threadIdx.x;
    const int lane = tid & 31;
    const int warp = tid >> 5;

    __shared__ float sh[KK][DD];
    __shared__ float sz[SS][DD];
    __shared__ float sw[SS][DD];
    __shared__ float logits[KK][SS];
    __shared__ float p[KK][SS];

    for (int i = tid; i < KK * (DD / 4); i += 256) {
        int k = i / (DD / 4), c4 = i % (DD / 4);
        reinterpret_cast<float4*>(sh[k])[c4] =
            reinterpret_cast<const float4*>(hidden + (size_t)(b * KK + k) * DD)[c4];
    }
    for (int i = tid; i < SS * (DD / 4); i += 256) {
        int s = i / (DD / 4), c4 = i % (DD / 4);
        reinterpret_cast<float4*>(sz[s])[c4] =
            reinterpret_cast<const float4*>(g_bufA + (size_t)(b * SS + s) * DD)[c4];
        reinterpret_cast<float4*>(sw[s])[c4] =
            reinterpret_cast<const float4*>(g_bufK + (size_t)(b * SS + s) * DD)[c4];
    }
    __syncthreads();

    for (int pr = warp; pr < KK * SS; pr += 8) {
        int k = pr >> 2, s = pr & 3;
        float d = warp_dot512(sh[k], sz[s]) * SCALE_F;
        if (lane == 0) logits[k][s] = d;
    }
    __syncthreads();

    if (tid < KK) {
        int k = tid;
        float m = NEG_INF;
        #pragma unroll
        for (int s = 0; s < SS; s++) m = fmaxf(m, logits[k][s]);
        float pe[SS], sum = 0.f;
        #pragma unroll
        for (int s = 0; s < SS; s++) { pe[s] = expf(logits[k][s] - m); sum += pe[s]; }
        float inv = 1.f / sum;
        #pragma unroll
        for (int s = 0; s < SS; s++) p[k][s] = pe[s] * inv;
    }
    __syncthreads();

    // warp-per-row: mix wsup, add residual, LayerNorm, store
    {
        const int k = warp;
        float pv[SS];
        #pragma unroll
        for (int s = 0; s < SS; s++) pv[s] = p[k][s];

        float vals[16];
        float lsum = 0.f, lsq = 0.f;
        #pragma unroll
        for (int j = 0; j < 16; j++) {
            int d = lane + j * 32;
            float a = 0.f;
            #pragma unroll
            for (int s = 0; s < SS; s++) a = fmaf(pv[s], sw[s][d], a);
            float x = sh[k][d] + a;
            vals[j] = x;
            lsum += x;
            lsq = fmaf(x, x, lsq);
        }
        lsum = warp_sum(lsum);
        lsq = warp_sum(lsq);
        float mu = lsum * (1.f / DD);
        float var = lsq * (1.f / DD) - mu * mu;
        float ri = rsqrtf(var + LN_EPS);

        float* orow = out + (size_t)(b * KK + k) * DD;
        #pragma unroll
        for (int j = 0; j < 16; j++) {
            int d = lane + j * 32;
            orow[d] = fmaf((vals[j] - mu) * ri, __ldg(&gam[d]), __ldg(&bet[d]));
        }
    }
}

// ---------------------------------------------------------------------------
// Launch — kernel launches ONLY; only harness pointers cross the boundary.
// ---------------------------------------------------------------------------
extern "C" void kernel_launch(void* const* d_in, const int* in_sizes, int n_in,
                              void* d_out, int out_size) {
    const float* hidden = (const float*)d_in[0];
    const int* mask = (const int*)d_in[1];
    const float* workspace = (const float*)d_in[2];
    const float* Wq_w = (const float*)d_in[3];
    const float* Wk_w = (const float*)d_in[4];
    const float* Wv_w = (const float*)d_in[5];
    const float* Wq_r = (const float*)d_in[6];
    const float* Wk_r = (const float*)d_in[7];
    const float* Wv_r = (const float*)d_in[8];
    const float* Wo = (const float*)d_in[9];
    const float* g_ws_p = (const float*)d_in[10];
    const float* b_ws_p = (const float*)d_in[11];
    const float* g_out_p = (const float*)d_in[12];
    const float* b_out_p = (const float*)d_in[13];
    float* out = (float*)d_out;

    dim3 sg(DD / 32, DD / 32);

    // Batch-independent precomputes (fp32 exact)
    aw_kernel<<<SS, 512>>>(workspace, Wq_w, Wk_w);        // g_Aw
    small_gemm<1><<<sg, 256>>>(Wq_r, Wk_r, 0);            // g_M   = Wq_r^T Wk_r
    small_gemm<0><<<sg, 256>>>(Wo, Wv_r, 1);              // g_Wov = Wo Wv_r

    // Write attention -> mhat (g_bufA)
    write_attn_kernel<<<BB, 256>>>(hidden, mask);

    // vmix = mhat @ Wv_w^T -> g_bufB, + LN stat partials   [32768, 512]
    {
        dim3 grid(MW / TM, DD / TN);
        gemm_tf32<<<grid, 256>>>(Wv_w, workspace, nullptr, nullptr,
                                 /*a*/0, /*w*/0, /*c*/0, /*mode*/1);
    }

    // mu, rs per row
    finalize_stats<<<MW / 256, 256>>>();

    // [z | wsup] = LN(ws+vmix) @ [M | Wov]^T -> g_bufA | g_bufK  [32768, 1024]
    {
        dim3 grid(MW / TM, (2 * DD) / TN);
        gemm_tf32<<<grid, 256>>>(nullptr, workspace, g_ws_p, b_ws_p,
                                 /*a*/1, /*w*/1, /*c*/1, /*mode*/2);
    }

    // Read attention + final LN -> out
    read_attn_ln_kernel<<<BB, 256>>>(hidden, g_out_p, b_out_p, out);
}

// round 11
// speedup vs baseline: 1.3275x; 1.3275x over previous
#include <cuda_runtime.h>
#include <math.h>
#include <stdint.h>

// Problem constants
#define BB 8192
#define KK 8
#define SS 4
#define DD 512
#define MW (BB * SS)                     // 32768 rows of workspace-space
#define SCALE_F 0.044194173824159216f    // 512^-0.5
#define LN_EPS 1e-5f
#define NEG_INF (__int_as_float(0xff800000))

// ---------------------------------------------------------------------------
// Scratch (device globals). NEVER passed as host-side kernel arguments —
// device code resolves them via selectors (host shadow symbols on GB300 ATS
// silently alias host memory).
// ---------------------------------------------------------------------------
__device__ float g_bufA[(size_t)MW * DD];        // mhat, then z
__device__ float g_bufB[(size_t)MW * DD];        // vmix, then wsu
__device__ float g_bufK[(size_t)MW * DD];        // wsup (projected wsu)
__device__ float g_Aw[SS * DD];                  // Wk_w^T Qws   [S,D]
__device__ float g_M[DD * DD];                   // Wq_r^T Wk_r  [D,D]
__device__ float g_Wov[DD * DD];                 // Wo Wv_r      [D,D]

// ---------------------------------------------------------------------------
// Helpers
// ---------------------------------------------------------------------------
__device__ __forceinline__ float warp_sum(float v) {
    #pragma unroll
    for (int o = 16; o; o >>= 1) v += __shfl_xor_sync(0xffffffffu, v, o);
    return v;
}

__device__ __forceinline__ float warp_dot512(const float* __restrict__ a,
                                             const float* __restrict__ b) {
    int lane = threadIdx.x & 31;
    const float4* a4 = reinterpret_cast<const float4*>(a);
    const float4* b4 = reinterpret_cast<const float4*>(b);
    float s = 0.f;
    #pragma unroll
    for (int i = 0; i < 4; i++) {
        float4 x = a4[lane + i * 32];
        float4 y = b4[lane + i * 32];
        s = fmaf(x.x, y.x, s);
        s = fmaf(x.y, y.y, s);
        s = fmaf(x.z, y.z, s);
        s = fmaf(x.w, y.w, s);
    }
    return warp_sum(s);
}

__device__ __forceinline__ uint32_t f2tf32(float f) {
    uint32_t r;
    asm("cvt.rna.tf32.f32 %0, %1;" : "=r"(r) : "f"(f));
    return r;
}

__device__ __forceinline__ void mma_tf32(float* c, const uint32_t* a,
                                         const uint32_t* b) {
    asm volatile(
        "mma.sync.aligned.m16n8k8.row.col.f32.tf32.tf32.f32 "
        "{%0,%1,%2,%3}, {%4,%5,%6,%7}, {%8,%9}, {%0,%1,%2,%3};\n"
        : "+f"(c[0]), "+f"(c[1]), "+f"(c[2]), "+f"(c[3])
        : "r"(a[0]), "r"(a[1]), "r"(a[2]), "r"(a[3]), "r"(b[0]), "r"(b[1]));
}

// ---------------------------------------------------------------------------
// Precompute Aw[s,d] = sum_e Qws[s,e]*Wk_w[e,d], Qws = ws @ Wq_w^T
// ---------------------------------------------------------------------------
__global__ __launch_bounds__(512) void aw_kernel(
    const float* __restrict__ ws, const float* __restrict__ Wq_w,
    const float* __restrict__ Wk_w) {
    const int s = blockIdx.x;
    const int tid = threadIdx.x;
    const int warp = tid >> 5;
    __shared__ float qs[DD];

    for (int e = warp; e < DD; e += 16) {
        float d = warp_dot512(ws + s * DD, Wq_w + (size_t)e * DD);
        if ((tid & 31) == 0) qs[e] = d;
    }
    __syncthreads();

    float acc = 0.f;
    for (int e = 0; e < DD; e++)
        acc = fmaf(qs[e], Wk_w[(size_t)e * DD + tid], acc);
    g_Aw[s * DD + tid] = acc;
}

// ---------------------------------------------------------------------------
// Small 512^3 GEMM (fp32, exact): C = opA(A)*B. c_sel: 0->g_M, 1->g_Wov.
// ---------------------------------------------------------------------------
template <int TRANSA>
__global__ __launch_bounds__(256) void small_gemm(
    const float* __restrict__ A, const float* __restrict__ B, int c_sel) {
    float* C = (c_sel == 0) ? g_M : g_Wov;
    __shared__ float As[32][33];
    __shared__ float Bs[32][33];
    const int m0 = blockIdx.y * 32;
    const int n0 = blockIdx.x * 32;
    const int tid = threadIdx.x;
    const int tr = tid >> 4;
    const int tc = tid & 15;

    float c00 = 0.f, c01 = 0.f, c10 = 0.f, c11 = 0.f;

    for (int e0 = 0; e0 < DD; e0 += 32) {
        #pragma unroll
        for (int i = tid; i < 1024; i += 256) {
            if (TRANSA) {
                int e = i >> 5, m = i & 31;
                As[e][m] = A[(size_t)(e0 + e) * DD + m0 + m];
            } else {
                int m = i >> 5, e = i & 31;
                As[e][m] = A[(size_t)(m0 + m) * DD + e0 + e];
            }
        }
        #pragma unroll
        for (int i = tid; i < 1024; i += 256) {
            int e = i >> 5, n = i & 31;
            Bs[e][n] = B[(size_t)(e0 + e) * DD + n0 + n];
        }
        __syncthreads();
        #pragma unroll
        for (int e = 0; e < 32; e++) {
            float a0 = As[e][tr * 2], a1 = As[e][tr * 2 + 1];
            float b0 = Bs[e][tc * 2], b1 = Bs[e][tc * 2 + 1];
            c00 = fmaf(a0, b0, c00);
            c01 = fmaf(a0, b1, c01);
            c10 = fmaf(a1, b0, c10);
            c11 = fmaf(a1, b1, c11);
        }
        __syncthreads();
    }
    C[(size_t)(m0 + tr * 2) * DD + n0 + tc * 2] = c00;
    C[(size_t)(m0 + tr * 2) * DD + n0 + tc * 2 + 1] = c01;
    C[(size_t)(m0 + tr * 2 + 1) * DD + n0 + tc * 2] = c10;
    C[(size_t)(m0 + tr * 2 + 1) * DD + n0 + tc * 2 + 1] = c11;
}

// ---------------------------------------------------------------------------
// tf32 tensor-core GEMM (NT): C[M,*] = A[M,512] @ W[n,:]^T   (Round 8 clean)
// Tiles: 128x128x32; 8 warps (2x4), warp-tile 64x32 via m16n8k8.
//   a_sel: 0=g_bufA 1=g_bufB
//   wmode: 0=Wext(N=512)  1=cols[0,512)->g_M, [512,1024)->g_Wov
//   cmode: 0=g_bufB        1=cols[0,512)->g_bufA, [512,1024)->g_bufK
// ---------------------------------------------------------------------------
#define TM 128
#define TN 128
#define TK 32

__global__ __launch_bounds__(256) void gemm_tf32(
    const float* __restrict__ Wext,
    int a_sel, int wmode, int cmode, int M) {
    const float* A = (a_sel == 0) ? g_bufA : g_bufB;
    const int bm = blockIdx.x * TM;
    const int bn = blockIdx.y * TN;

    const float* W;
    int wn0;
    if (wmode == 0) { W = Wext; wn0 = bn; }
    else { W = (bn < 512) ? g_M : g_Wov; wn0 = bn & 511; }

    float* C;
    int cn0;
    if (cmode == 0) { C = g_bufB; cn0 = bn; }
    else { C = (bn < 512) ? g_bufA : g_bufK; cn0 = bn & 511; }

    __shared__ uint32_t As[TM][36];   // padded: conflict-free fragment loads
    __shared__ uint32_t Bs[TN][36];

    const int tid = threadIdx.x;
    const int lane = tid & 31;
    const int warp = tid >> 5;
    const int wm = warp & 1;          // 2 warps along M (64 rows each)
    const int wn = warp >> 1;         // 4 warps along N (32 cols each)
    const int gid = lane >> 2;
    const int tig = lane & 3;

    float acc[4][4][4];
    #pragma unroll
    for (int i = 0; i < 4; i++)
        #pragma unroll
        for (int j = 0; j < 4; j++)
            #pragma unroll
            for (int r = 0; r < 4; r++) acc[i][j][r] = 0.f;

    float4 ra[4], rw[4];
    #pragma unroll
    for (int i = 0; i < 4; i++) {
        int idx = tid + i * 256;
        int r = idx >> 3, c = (idx & 7) * 4;
        ra[i] = *reinterpret_cast<const float4*>(A + (size_t)(bm + r) * DD + c);
        rw[i] = *reinterpret_cast<const float4*>(W + (size_t)(wn0 + r) * DD + c);
    }

    for (int t = 0; t < DD / TK; t++) {
        #pragma unroll
        for (int i = 0; i < 4; i++) {
            int idx = tid + i * 256;
            int r = idx >> 3, c = (idx & 7) * 4;
            As[r][c + 0] = f2tf32(ra[i].x); As[r][c + 1] = f2tf32(ra[i].y);
            As[r][c + 2] = f2tf32(ra[i].z); As[r][c + 3] = f2tf32(ra[i].w);
            Bs[r][c + 0] = f2tf32(rw[i].x); Bs[r][c + 1] = f2tf32(rw[i].y);
            Bs[r][c + 2] = f2tf32(rw[i].z); Bs[r][c + 3] = f2tf32(rw[i].w);
        }
        __syncthreads();

        if (t + 1 < DD / TK) {
            int k0 = (t + 1) * TK;
            #pragma unroll
            for (int i = 0; i < 4; i++) {
                int idx = tid + i * 256;
                int r = idx >> 3, c = (idx & 7) * 4;
                ra[i] = *reinterpret_cast<const float4*>(
                    A + (size_t)(bm + r) * DD + k0 + c);
                rw[i] = *reinterpret_cast<const float4*>(
                    W + (size_t)(wn0 + r) * DD + k0 + c);
            }
        }

        #pragma unroll
        for (int ks = 0; ks < 4; ks++) {
            uint32_t af[4][4], bf[4][2];
            #pragma unroll
            for (int mt = 0; mt < 4; mt++) {
                int r0 = wm * 64 + mt * 16 + gid;
                af[mt][0] = As[r0][ks * 8 + tig];
                af[mt][1] = As[r0 + 8][ks * 8 + tig];
                af[mt][2] = As[r0][ks * 8 + tig + 4];
                af[mt][3] = As[r0 + 8][ks * 8 + tig + 4];
            }
            #pragma unroll
            for (int nt = 0; nt < 4; nt++) {
                int c0 = wn * 32 + nt * 8 + gid;
                bf[nt][0] = Bs[c0][ks * 8 + tig];
                bf[nt][1] = Bs[c0][ks * 8 + tig + 4];
            }
            #pragma unroll
            for (int mt = 0; mt < 4; mt++)
                #pragma unroll
                for (int nt = 0; nt < 4; nt++)
                    mma_tf32(acc[mt][nt], af[mt], bf[nt]);
        }
        __syncthreads();
    }

    #pragma unroll
    for (int mt = 0; mt < 4; mt++) {
        #pragma unroll
        for (int nt = 0; nt < 4; nt++) {
            int grow = bm + wm * 64 + mt * 16 + gid;
            int gcol = cn0 + wn * 32 + nt * 8 + 2 * tig;
            *reinterpret_cast<float2*>(&C[(size_t)grow * DD + gcol]) =
                make_float2(acc[mt][nt][0], acc[mt][nt][1]);
            *reinterpret_cast<float2*>(&C[(size_t)(grow + 8) * DD + gcol]) =
                make_float2(acc[mt][nt][2], acc[mt][nt][3]);
        }
    }
}

// ---------------------------------------------------------------------------
// Write attention -> mhat (g_bufA). One block per batch b.
// ---------------------------------------------------------------------------
__global__ __launch_bounds__(256) void write_attn_kernel(
    const float* __restrict__ hidden,
    const int* __restrict__ mask) {
    const int b = blockIdx.x;
    const int tid = threadIdx.x;
    const int warp = tid >> 5;

    __shared__ float sh[KK][DD];
    __shared__ float logits[SS][KK];
    __shared__ float p[SS][KK];
    __shared__ int smask[KK];

    if (tid < KK) smask[tid] = mask[b * KK + tid];

    for (int i = tid; i < KK * (DD / 4); i += 256) {
        int k = i / (DD / 4), c4 = i % (DD / 4);
        reinterpret_cast<float4*>(sh[k])[c4] =
            reinterpret_cast<const float4*>(hidden + (size_t)(b * KK + k) * DD)[c4];
    }
    __syncthreads();

    for (int pr = warp; pr < SS * KK; pr += 8) {
        int s = pr >> 3, k = pr & 7;
        float d = warp_dot512(g_Aw + s * DD, sh[k]) * SCALE_F;
        if ((tid & 31) == 0) logits[s][k] = d;
    }
    __syncthreads();

    if (tid < SS) {
        int s = tid;
        float m = NEG_INF;
        #pragma unroll
        for (int k = 0; k < KK; k++)
            if (smask[k] != 0) m = fmaxf(m, logits[s][k]);
        float pe[KK], sum = 0.f;
        #pragma unroll
        for (int k = 0; k < KK; k++) {
            float e = (smask[k] != 0) ? expf(logits[s][k] - m) : 0.f;
            pe[k] = e; sum += e;
        }
        float inv = (sum > 0.f) ? 1.f / sum : 0.f;
        #pragma unroll
        for (int k = 0; k < KK; k++) p[s][k] = pe[k] * inv;
    }
    __syncthreads();

    #pragma unroll
    for (int s = 0; s < SS; s++) {
        #pragma unroll
        for (int h = 0; h < 2; h++) {
            int d = tid + h * 256;
            float acc = 0.f;
            #pragma unroll
            for (int k = 0; k < KK; k++) acc = fmaf(p[s][k], sh[k][d], acc);
            g_bufA[(size_t)(b * SS + s) * DD + d] = acc;
        }
    }
}

// ---------------------------------------------------------------------------
// wsu = LN(ws[s] + vmix) in-place on g_bufB. One block per (b,s) row.
// ---------------------------------------------------------------------------
__global__ __launch_bounds__(256) void ln_ws_kernel(
    const float* __restrict__ workspace,
    const float* __restrict__ g, const float* __restrict__ bb) {
    const size_t row = blockIdx.x;
    const int s = (int)(row & (SS - 1));
    const int tid = threadIdx.x;
    const int warp = tid >> 5;
    __shared__ float s_part[2][8];
    __shared__ float s_stats[2];

    float vv[2];
    #pragma unroll
    for (int h = 0; h < 2; h++) {
        int d = tid + h * 256;
        vv[h] = workspace[s * DD + d] + g_bufB[row * DD + d];
    }
    float sum = warp_sum(vv[0] + vv[1]);
    float sq = warp_sum(vv[0] * vv[0] + vv[1] * vv[1]);
    if ((tid & 31) == 0) { s_part[0][warp] = sum; s_part[1][warp] = sq; }
    __syncthreads();
    if (tid == 0) {
        float ts = 0.f, tq = 0.f;
        #pragma unroll
        for (int w = 0; w < 8; w++) { ts += s_part[0][w]; tq += s_part[1][w]; }
        float mu = ts * (1.f / DD);
        float var = tq * (1.f / DD) - mu * mu;
        s_stats[0] = mu; s_stats[1] = rsqrtf(var + LN_EPS);
    }
    __syncthreads();
    float mu = s_stats[0], ri = s_stats[1];
    #pragma unroll
    for (int h = 0; h < 2; h++) {
        int d = tid + h * 256;
        g_bufB[row * DD + d] = (vv[h] - mu) * ri * g[d] + bb[d];
    }
}

// ---------------------------------------------------------------------------
// Read attention + FINAL LN fused. One block per batch b.
//   logits[k,s] = SCALE * h[b,k] . z[b,s]  (z in g_bufA); softmax over s
//   x[k,:] = h[b,k,:] + sum_s p[k,s]*wsup[b,s,:]; out = LN(x)
// ---------------------------------------------------------------------------
__global__ __launch_bounds__(256) void read_attn_ln_kernel(
    const float* __restrict__ hidden,
    const float* __restrict__ gam, const float* __restrict__ bet,
    float* __restrict__ out) {
    const int b = blockIdx.x;
    const int tid = threadIdx.x;
    const int lane = tid & 31;
    const int warp = tid >> 5;

    __shared__ float sh[KK][DD];
    __shared__ float sz[SS][DD];
    __shared__ float sw[SS][DD];
    __shared__ float logits[KK][SS];
    __shared__ float p[KK][SS];

    for (int i = tid; i < KK * (DD / 4); i += 256) {
        int k = i / (DD / 4), c4 = i % (DD / 4);
        reinterpret_cast<float4*>(sh[k])[c4] =
            reinterpret_cast<const float4*>(hidden + (size_t)(b * KK + k) * DD)[c4];
    }
    for (int i = tid; i < SS * (DD / 4); i += 256) {
        int s = i / (DD / 4), c4 = i % (DD / 4);
        reinterpret_cast<float4*>(sz[s])[c4] =
            reinterpret_cast<const float4*>(g_bufA + (size_t)(b * SS + s) * DD)[c4];
        reinterpret_cast<float4*>(sw[s])[c4] =
            reinterpret_cast<const float4*>(g_bufK + (size_t)(b * SS + s) * DD)[c4];
    }
    __syncthreads();

    for (int pr = warp; pr < KK * SS; pr += 8) {
        int k = pr >> 2, s = pr & 3;
        float d = warp_dot512(sh[k], sz[s]) * SCALE_F;
        if (lane == 0) logits[k][s] = d;
    }
    __syncthreads();

    if (tid < KK) {
        int k = tid;
        float m = NEG_INF;
        #pragma unroll
        for (int s = 0; s < SS; s++) m = fmaxf(m, logits[k][s]);
        float pe[SS], sum = 0.f;
        #pragma unroll
        for (int s = 0; s < SS; s++) { pe[s] = expf(logits[k][s] - m); sum += pe[s]; }
        float inv = 1.f / sum;
        #pragma unroll
        for (int s = 0; s < SS; s++) p[k][s] = pe[s] * inv;
    }
    __syncthreads();

    // warp-per-row: mix wsup, add residual, LayerNorm, store
    {
        const int k = warp;
        float pv[SS];
        #pragma unroll
        for (int s = 0; s < SS; s++) pv[s] = p[k][s];

        float vals[16];
        float lsum = 0.f, lsq = 0.f;
        #pragma unroll
        for (int j = 0; j < 16; j++) {
            int d = lane + j * 32;
            float a = 0.f;
            #pragma unroll
            for (int s = 0; s < SS; s++) a = fmaf(pv[s], sw[s][d], a);
            float x = sh[k][d] + a;
            vals[j] = x;
            lsum += x;
            lsq = fmaf(x, x, lsq);
        }
        lsum = warp_sum(lsum);
        lsq = warp_sum(lsq);
        float mu = lsum * (1.f / DD);
        float var = lsq * (1.f / DD) - mu * mu;
        float ri = rsqrtf(var + LN_EPS);

        float* orow = out + (size_t)(b * KK + k) * DD;
        #pragma unroll
        for (int j = 0; j < 16; j++) {
            int d = lane + j * 32;
            orow[d] = fmaf((vals[j] - mu) * ri, __ldg(&gam[d]), __ldg(&bet[d]));
        }
    }
}

// ---------------------------------------------------------------------------
// Launch — kernel launches ONLY; only harness pointers cross the boundary.
// ---------------------------------------------------------------------------
extern "C" void kernel_launch(void* const* d_in, const int* in_sizes, int n_in,
                              void* d_out, int out_size) {
    const float* hidden = (const float*)d_in[0];
    const int* mask = (const int*)d_in[1];
    const float* workspace = (const float*)d_in[2];
    const float* Wq_w = (const float*)d_in[3];
    const float* Wk_w = (const float*)d_in[4];
    const float* Wv_w = (const float*)d_in[5];
    const float* Wq_r = (const float*)d_in[6];
    const float* Wk_r = (const float*)d_in[7];
    const float* Wv_r = (const float*)d_in[8];
    const float* Wo = (const float*)d_in[9];
    const float* g_ws_p = (const float*)d_in[10];
    const float* b_ws_p = (const float*)d_in[11];
    const float* g_out_p = (const float*)d_in[12];
    const float* b_out_p = (const float*)d_in[13];
    float* out = (float*)d_out;

    dim3 sg(DD / 32, DD / 32);

    // Batch-independent precomputes (fp32 exact)
    aw_kernel<<<SS, 512>>>(workspace, Wq_w, Wk_w);        // g_Aw
    small_gemm<1><<<sg, 256>>>(Wq_r, Wk_r, 0);            // g_M   = Wq_r^T Wk_r
    small_gemm<0><<<sg, 256>>>(Wo, Wv_r, 1);              // g_Wov = Wo Wv_r

    // Write attention -> mhat (g_bufA)
    write_attn_kernel<<<BB, 256>>>(hidden, mask);

    // vmix = mhat @ Wv_w^T -> g_bufB   [32768, 512]  (tf32 TC)
    {
        dim3 grid(MW / TM, DD / TN);
        gemm_tf32<<<grid, 256>>>(Wv_w, /*a*/0, /*w*/0, /*c*/0, MW);
    }

    // wsu = LN(ws + vmix), in-place g_bufB
    ln_ws_kernel<<<MW, 256>>>(workspace, g_ws_p, b_ws_p);

    // [z | wsup] = wsu @ [M | Wov]^T -> g_bufA | g_bufK  [32768, 1024] (tf32 TC)
    {
        dim3 grid(MW / TM, (2 * DD) / TN);
        gemm_tf32<<<grid, 256>>>(nullptr, /*a*/1, /*w*/1, /*c*/1, MW);
    }

    // Read attention + final LN -> out
    read_attn_ln_kernel<<<BB, 256>>>(hidden, g_out_p, b_out_p, out);
}

// round 12
// speedup vs baseline: 1.4230x; 1.0719x over previous
#include <cuda_runtime.h>
#include <math.h>
#include <stdint.h>

// Problem constants
#define BB 8192
#define KK 8
#define SS 4
#define DD 512
#define MW (BB * SS)                     // 32768 rows of workspace-space
#define SCALE_F 0.044194173824159216f    // 512^-0.5
#define LN_EPS 1e-5f
#define NEG_INF (__int_as_float(0xff800000))

// ---------------------------------------------------------------------------
// Scratch (device globals). NEVER passed as host-side kernel arguments —
// device code resolves them via selectors (host shadow symbols on GB300 ATS
// silently alias host memory).
// ---------------------------------------------------------------------------
__device__ float g_bufA[(size_t)MW * DD];        // mhat, then z
__device__ float g_bufB[(size_t)MW * DD];        // vmix, then wsu
__device__ float g_bufK[(size_t)MW * DD];        // wsup (projected wsu)
__device__ float g_Aw[SS * DD];                  // Wk_w^T Qws   [S,D]
__device__ float g_M[DD * DD];                   // Wq_r^T Wk_r  [D,D] (tf32-rounded)
__device__ float g_Wov[DD * DD];                 // Wo Wv_r      [D,D] (tf32-rounded)
__device__ float g_Wvw[DD * DD];                 // Wv_w          (tf32-rounded copy)

// ---------------------------------------------------------------------------
// Helpers
// ---------------------------------------------------------------------------
__device__ __forceinline__ float warp_sum(float v) {
    #pragma unroll
    for (int o = 16; o; o >>= 1) v += __shfl_xor_sync(0xffffffffu, v, o);
    return v;
}

__device__ __forceinline__ float warp_dot512(const float* __restrict__ a,
                                             const float* __restrict__ b) {
    int lane = threadIdx.x & 31;
    const float4* a4 = reinterpret_cast<const float4*>(a);
    const float4* b4 = reinterpret_cast<const float4*>(b);
    float s = 0.f;
    #pragma unroll
    for (int i = 0; i < 4; i++) {
        float4 x = a4[lane + i * 32];
        float4 y = b4[lane + i * 32];
        s = fmaf(x.x, y.x, s);
        s = fmaf(x.y, y.y, s);
        s = fmaf(x.z, y.z, s);
        s = fmaf(x.w, y.w, s);
    }
    return warp_sum(s);
}

// round-to-nearest tf32, returned as float bit-pattern
__device__ __forceinline__ float rtf32(float f) {
    uint32_t r;
    asm("cvt.rna.tf32.f32 %0, %1;" : "=r"(r) : "f"(f));
    return __uint_as_float(r);
}

__device__ __forceinline__ void mma_tf32(float* c, const uint32_t* a,
                                         const uint32_t* b) {
    asm volatile(
        "mma.sync.aligned.m16n8k8.row.col.f32.tf32.tf32.f32 "
        "{%0,%1,%2,%3}, {%4,%5,%6,%7}, {%8,%9}, {%0,%1,%2,%3};\n"
        : "+f"(c[0]), "+f"(c[1]), "+f"(c[2]), "+f"(c[3])
        : "r"(a[0]), "r"(a[1]), "r"(a[2]), "r"(a[3]), "r"(b[0]), "r"(b[1]));
}

__device__ __forceinline__ void cp16(void* smem_dst, const void* gsrc) {
    uint32_t s = (uint32_t)__cvta_generic_to_shared(smem_dst);
    asm volatile("cp.async.cg.shared.global [%0], [%1], 16;\n"
                 :: "r"(s), "l"(gsrc));
}

// ---------------------------------------------------------------------------
// Precompute Aw[s,d] = sum_e Qws[s,e]*Wk_w[e,d], Qws = ws @ Wq_w^T
// ---------------------------------------------------------------------------
__global__ __launch_bounds__(512) void aw_kernel(
    const float* __restrict__ ws, const float* __restrict__ Wq_w,
    const float* __restrict__ Wk_w) {
    const int s = blockIdx.x;
    const int tid = threadIdx.x;
    const int warp = tid >> 5;
    __shared__ float qs[DD];

    for (int e = warp; e < DD; e += 16) {
        float d = warp_dot512(ws + s * DD, Wq_w + (size_t)e * DD);
        if ((tid & 31) == 0) qs[e] = d;
    }
    __syncthreads();

    float acc = 0.f;
    for (int e = 0; e < DD; e++)
        acc = fmaf(qs[e], Wk_w[(size_t)e * DD + tid], acc);
    g_Aw[s * DD + tid] = acc;
}

// ---------------------------------------------------------------------------
// Convert Wv_w -> tf32-rounded scratch copy (GEMM1 B operand).
// ---------------------------------------------------------------------------
__global__ __launch_bounds__(256) void cvt_w_kernel(const float* __restrict__ src) {
    size_t i = ((size_t)blockIdx.x * 256 + threadIdx.x) * 4;
    float4 v = *reinterpret_cast<const float4*>(src + i);
    float4 o;
    o.x = rtf32(v.x); o.y = rtf32(v.y); o.z = rtf32(v.z); o.w = rtf32(v.w);
    *reinterpret_cast<float4*>(g_Wvw + i) = o;
}

// ---------------------------------------------------------------------------
// Small 512^3 GEMM (fp32 accumulate, tf32-rounded store).
// c_sel: 0->g_M, 1->g_Wov.
// ---------------------------------------------------------------------------
template <int TRANSA>
__global__ __launch_bounds__(256) void small_gemm(
    const float* __restrict__ A, const float* __restrict__ B, int c_sel) {
    float* C = (c_sel == 0) ? g_M : g_Wov;
    __shared__ float As[32][33];
    __shared__ float Bs[32][33];
    const int m0 = blockIdx.y * 32;
    const int n0 = blockIdx.x * 32;
    const int tid = threadIdx.x;
    const int tr = tid >> 4;
    const int tc = tid & 15;

    float c00 = 0.f, c01 = 0.f, c10 = 0.f, c11 = 0.f;

    for (int e0 = 0; e0 < DD; e0 += 32) {
        #pragma unroll
        for (int i = tid; i < 1024; i += 256) {
            if (TRANSA) {
                int e = i >> 5, m = i & 31;
                As[e][m] = A[(size_t)(e0 + e) * DD + m0 + m];
            } else {
                int m = i >> 5, e = i & 31;
                As[e][m] = A[(size_t)(m0 + m) * DD + e0 + e];
            }
        }
        #pragma unroll
        for (int i = tid; i < 1024; i += 256) {
            int e = i >> 5, n = i & 31;
            Bs[e][n] = B[(size_t)(e0 + e) * DD + n0 + n];
        }
        __syncthreads();
        #pragma unroll
        for (int e = 0; e < 32; e++) {
            float a0 = As[e][tr * 2], a1 = As[e][tr * 2 + 1];
            float b0 = Bs[e][tc * 2], b1 = Bs[e][tc * 2 + 1];
            c00 = fmaf(a0, b0, c00);
            c01 = fmaf(a0, b1, c01);
            c10 = fmaf(a1, b0, c10);
            c11 = fmaf(a1, b1, c11);
        }
        __syncthreads();
    }
    C[(size_t)(m0 + tr * 2) * DD + n0 + tc * 2] = rtf32(c00);
    C[(size_t)(m0 + tr * 2) * DD + n0 + tc * 2 + 1] = rtf32(c01);
    C[(size_t)(m0 + tr * 2 + 1) * DD + n0 + tc * 2] = rtf32(c10);
    C[(size_t)(m0 + tr * 2 + 1) * DD + n0 + tc * 2 + 1] = rtf32(c11);
}

// ---------------------------------------------------------------------------
// tf32 tensor-core GEMM (NT): C[M,*] = A[M,512] @ W[n,:]^T
// 128x128 block tile, 4 warps of 64x64, TK=16, 2-stage cp.async pipeline.
// Inputs are ALREADY tf32-rounded (producers round) — no conversion here.
//   a_sel: 0=g_bufA 1=g_bufB
//   wmode: 0=g_Wvw(N=512)  1=cols[0,512)->g_M, [512,1024)->g_Wov
//   cmode: 0=g_bufB        1=cols[0,512)->g_bufA, [512,1024)->g_bufK
// ---------------------------------------------------------------------------
#define TM 128
#define TN 128
#define TKS 16

__global__ __launch_bounds__(128) void gemm_tf32(
    int a_sel, int wmode, int cmode, int M) {
    const float* A = (a_sel == 0) ? g_bufA : g_bufB;
    const int bm = blockIdx.x * TM;
    const int bn = blockIdx.y * TN;

    const float* W;
    int wn0;
    if (wmode == 0) { W = g_Wvw; wn0 = bn; }
    else { W = (bn < 512) ? g_M : g_Wov; wn0 = bn & 511; }

    float* C;
    int cn0;
    if (cmode == 0) { C = g_bufB; cn0 = bn; }
    else { C = (bn < 512) ? g_bufA : g_bufK; cn0 = bn & 511; }

    __shared__ uint32_t As[2][TM][20];   // stride 20: conflict-free frags
    __shared__ uint32_t Bs[2][TN][20];

    const int tid = threadIdx.x;
    const int lane = tid & 31;
    const int warp = tid >> 5;
    const int wm = warp & 1;          // 2 warps along M (64 rows each)
    const int wn = warp >> 1;         // 2 warps along N (64 cols each)
    const int gid = lane >> 2;
    const int tig = lane & 3;

    // cp.async mapping: thread covers 4 A-rows and 4 B-rows, one 16B seg each
    const int cr = tid >> 2;          // 0..31
    const int cs = (tid & 3) * 4;     // 0,4,8,12
    const float* arow = A + (size_t)(bm + cr) * DD + cs;
    const float* wrow = W + (size_t)(wn0 + cr) * DD + cs;

    float acc[4][8][4];
    #pragma unroll
    for (int i = 0; i < 4; i++)
        #pragma unroll
        for (int j = 0; j < 8; j++)
            #pragma unroll
            for (int r = 0; r < 4; r++) acc[i][j][r] = 0.f;

    // prologue: issue stages 0 and 1
    #pragma unroll
    for (int s = 0; s < 2; s++) {
        int k0 = s * TKS;
        #pragma unroll
        for (int i = 0; i < 4; i++) {
            cp16(&As[s][cr + i * 32][cs], arow + (size_t)i * 32 * DD + k0);
            cp16(&Bs[s][cr + i * 32][cs], wrow + (size_t)i * 32 * DD + k0);
        }
        asm volatile("cp.async.commit_group;\n" ::: "memory");
    }

    for (int t = 0; t < DD / TKS; t++) {
        if (t < DD / TKS - 1)
            asm volatile("cp.async.wait_group 1;\n" ::: "memory");
        else
            asm volatile("cp.async.wait_group 0;\n" ::: "memory");
        __syncthreads();

        const int buf = t & 1;
        #pragma unroll
        for (int ks = 0; ks < 2; ks++) {
            uint32_t af[4][4], bf[8][2];
            #pragma unroll
            for (int mt = 0; mt < 4; mt++) {
                int r0 = wm * 64 + mt * 16 + gid;
                af[mt][0] = As[buf][r0][ks * 8 + tig];
                af[mt][1] = As[buf][r0 + 8][ks * 8 + tig];
                af[mt][2] = As[buf][r0][ks * 8 + tig + 4];
                af[mt][3] = As[buf][r0 + 8][ks * 8 + tig + 4];
            }
            #pragma unroll
            for (int nt = 0; nt < 8; nt++) {
                int c0 = wn * 64 + nt * 8 + gid;
                bf[nt][0] = Bs[buf][c0][ks * 8 + tig];
                bf[nt][1] = Bs[buf][c0][ks * 8 + tig + 4];
            }
            #pragma unroll
            for (int mt = 0; mt < 4; mt++)
                #pragma unroll
                for (int nt = 0; nt < 8; nt++)
                    mma_tf32(acc[mt][nt], af[mt], bf[nt]);
        }
        __syncthreads();

        if (t + 2 < DD / TKS) {
            int k0 = (t + 2) * TKS;
            #pragma unroll
            for (int i = 0; i < 4; i++) {
                cp16(&As[buf][cr + i * 32][cs], arow + (size_t)i * 32 * DD + k0);
                cp16(&Bs[buf][cr + i * 32][cs], wrow + (size_t)i * 32 * DD + k0);
            }
            asm volatile("cp.async.commit_group;\n" ::: "memory");
        }
    }

    #pragma unroll
    for (int mt = 0; mt < 4; mt++) {
        #pragma unroll
        for (int nt = 0; nt < 8; nt++) {
            int grow = bm + wm * 64 + mt * 16 + gid;
            int gcol = cn0 + wn * 64 + nt * 8 + 2 * tig;
            *reinterpret_cast<float2*>(&C[(size_t)grow * DD + gcol]) =
                make_float2(acc[mt][nt][0], acc[mt][nt][1]);
            *reinterpret_cast<float2*>(&C[(size_t)(grow + 8) * DD + gcol]) =
                make_float2(acc[mt][nt][2], acc[mt][nt][3]);
        }
    }
}

// ---------------------------------------------------------------------------
// Write attention -> mhat (g_bufA, tf32-rounded). One block per batch b.
// ---------------------------------------------------------------------------
__global__ __launch_bounds__(256) void write_attn_kernel(
    const float* __restrict__ hidden,
    const int* __restrict__ mask) {
    const int b = blockIdx.x;
    const int tid = threadIdx.x;
    const int warp = tid >> 5;

    __shared__ float sh[KK][DD];
    __shared__ float logits[SS][KK];
    __shared__ float p[SS][KK];
    __shared__ int smask[KK];

    if (tid < KK) smask[tid] = mask[b * KK + tid];

    for (int i = tid; i < KK * (DD / 4); i += 256) {
        int k = i / (DD / 4), c4 = i % (DD / 4);
        reinterpret_cast<float4*>(sh[k])[c4] =
            reinterpret_cast<const float4*>(hidden + (size_t)(b * KK + k) * DD)[c4];
    }
    __syncthreads();

    for (int pr = warp; pr < SS * KK; pr += 8) {
        int s = pr >> 3, k = pr & 7;
        float d = warp_dot512(g_Aw + s * DD, sh[k]) * SCALE_F;
        if ((tid & 31) == 0) logits[s][k] = d;
    }
    __syncthreads();

    if (tid < SS) {
        int s = tid;
        float m = NEG_INF;
        #pragma unroll
        for (int k = 0; k < KK; k++)
            if (smask[k] != 0) m = fmaxf(m, logits[s][k]);
        float pe[KK], sum = 0.f;
        #pragma unroll
        for (int k = 0; k < KK; k++) {
            float e = (smask[k] != 0) ? expf(logits[s][k] - m) : 0.f;
            pe[k] = e; sum += e;
        }
        float inv = (sum > 0.f) ? 1.f / sum : 0.f;
        #pragma unroll
        for (int k = 0; k < KK; k++) p[s][k] = pe[k] * inv;
    }
    __syncthreads();

    #pragma unroll
    for (int s = 0; s < SS; s++) {
        #pragma unroll
        for (int h = 0; h < 2; h++) {
            int d = tid + h * 256;
            float acc = 0.f;
            #pragma unroll
            for (int k = 0; k < KK; k++) acc = fmaf(p[s][k], sh[k][d], acc);
            g_bufA[(size_t)(b * SS + s) * DD + d] = rtf32(acc);
        }
    }
}

// ---------------------------------------------------------------------------
// wsu = LN(ws[s] + vmix) in-place on g_bufB (tf32-rounded store).
// ---------------------------------------------------------------------------
__global__ __launch_bounds__(256) void ln_ws_kernel(
    const float* __restrict__ workspace,
    const float* __restrict__ g, const float* __restrict__ bb) {
    const size_t row = blockIdx.x;
    const int s = (int)(row & (SS - 1));
    const int tid = threadIdx.x;
    const int warp = tid >> 5;
    __shared__ float s_part[2][8];
    __shared__ float s_stats[2];

    float vv[2];
    #pragma unroll
    for (int h = 0; h < 2; h++) {
        int d = tid + h * 256;
        vv[h] = workspace[s * DD + d] + g_bufB[row * DD + d];
    }
    float sum = warp_sum(vv[0] + vv[1]);
    float sq = warp_sum(vv[0] * vv[0] + vv[1] * vv[1]);
    if ((tid & 31) == 0) { s_part[0][warp] = sum; s_part[1][warp] = sq; }
    __syncthreads();
    if (tid == 0) {
        float ts = 0.f, tq = 0.f;
        #pragma unroll
        for (int w = 0; w < 8; w++) { ts += s_part[0][w]; tq += s_part[1][w]; }
        float mu = ts * (1.f / DD);
        float var = tq * (1.f / DD) - mu * mu;
        s_stats[0] = mu; s_stats[1] = rsqrtf(var + LN_EPS);
    }
    __syncthreads();
    float mu = s_stats[0], ri = s_stats[1];
    #pragma unroll
    for (int h = 0; h < 2; h++) {
        int d = tid + h * 256;
        g_bufB[row * DD + d] = rtf32((vv[h] - mu) * ri * g[d] + bb[d]);
    }
}

// ---------------------------------------------------------------------------
// Read attention + FINAL LN fused. One block per batch b.
// ---------------------------------------------------------------------------
__global__ __launch_bounds__(256) void read_attn_ln_kernel(
    const float* __restrict__ hidden,
    const float* __restrict__ gam, const float* __restrict__ bet,
    float* __restrict__ out) {
    const int b = blockIdx.x;
    const int tid = threadIdx.x;
    const int lane = tid & 31;
    const int warp = tid >> 5;

    __shared__ float sh[KK][DD];
    __shared__ float sz[SS][DD];
    __shared__ float sw[SS][DD];
    __shared__ float logits[KK][SS];
    __shared__ float p[KK][SS];

    for (int i = tid; i < KK * (DD / 4); i += 256) {
        int k = i / (DD / 4), c4 = i % (DD / 4);
        reinterpret_cast<float4*>(sh[k])[c4] =
            reinterpret_cast<const float4*>(hidden + (size_t)(b * KK + k) * DD)[c4];
    }
    for (int i = tid; i < SS * (DD / 4); i += 256) {
        int s = i / (DD / 4), c4 = i % (DD / 4);
        reinterpret_cast<float4*>(sz[s])[c4] =
            reinterpret_cast<const float4*>(g_bufA + (size_t)(b * SS + s) * DD)[c4];
        reinterpret_cast<float4*>(sw[s])[c4] =
            reinterpret_cast<const float4*>(g_bufK + (size_t)(b * SS + s) * DD)[c4];
    }
    __syncthreads();

    for (int pr = warp; pr < KK * SS; pr += 8) {
        int k = pr >> 2, s = pr & 3;
        float d = warp_dot512(sh[k], sz[s]) * SCALE_F;
        if (lane == 0) logits[k][s] = d;
    }
    __syncthreads();

    if (tid < KK) {
        int k = tid;
        float m = NEG_INF;
        #pragma unroll
        for (int s = 0; s < SS; s++) m = fmaxf(m, logits[k][s]);
        float pe[SS], sum = 0.f;
        #pragma unroll
        for (int s = 0; s < SS; s++) { pe[s] = expf(logits[k][s] - m); sum += pe[s]; }
        float inv = 1.f / sum;
        #pragma unroll
        for (int s = 0; s < SS; s++) p[k][s] = pe[s] * inv;
    }
    __syncthreads();

    {
        const int k = warp;
        float pv[SS];
        #pragma unroll
        for (int s = 0; s < SS; s++) pv[s] = p[k][s];

        float vals[16];
        float lsum = 0.f, lsq = 0.f;
        #pragma unroll
        for (int j = 0; j < 16; j++) {
            int d = lane + j * 32;
            float a = 0.f;
            #pragma unroll
            for (int s = 0; s < SS; s++) a = fmaf(pv[s], sw[s][d], a);
            float x = sh[k][d] + a;
            vals[j] = x;
            lsum += x;
            lsq = fmaf(x, x, lsq);
        }
        lsum = warp_sum(lsum);
        lsq = warp_sum(lsq);
        float mu = lsum * (1.f / DD);
        float var = lsq * (1.f / DD) - mu * mu;
        float ri = rsqrtf(var + LN_EPS);

        float* orow = out + (size_t)(b * KK + k) * DD;
        #pragma unroll
        for (int j = 0; j < 16; j++) {
            int d = lane + j * 32;
            orow[d] = fmaf((vals[j] - mu) * ri, __ldg(&gam[d]), __ldg(&bet[d]));
        }
    }
}

// ---------------------------------------------------------------------------
// Launch — kernel launches ONLY; only harness pointers cross the boundary.
// ---------------------------------------------------------------------------
extern "C" void kernel_launch(void* const* d_in, const int* in_sizes, int n_in,
                              void* d_out, int out_size) {
    const float* hidden = (const float*)d_in[0];
    const int* mask = (const int*)d_in[1];
    const float* workspace = (const float*)d_in[2];
    const float* Wq_w = (const float*)d_in[3];
    const float* Wk_w = (const float*)d_in[4];
    const float* Wv_w = (const float*)d_in[5];
    const float* Wq_r = (const float*)d_in[6];
    const float* Wk_r = (const float*)d_in[7];
    const float* Wv_r = (const float*)d_in[8];
    const float* Wo = (const float*)d_in[9];
    const float* g_ws_p = (const float*)d_in[10];
    const float* b_ws_p = (const float*)d_in[11];
    const float* g_out_p = (const float*)d_in[12];
    const float* b_out_p = (const float*)d_in[13];
    float* out = (float*)d_out;

    dim3 sg(DD / 32, DD / 32);

    // Batch-independent precomputes
    aw_kernel<<<SS, 512>>>(workspace, Wq_w, Wk_w);        // g_Aw (fp32)
    cvt_w_kernel<<<(DD * DD) / 1024, 256>>>(Wv_w);        // g_Wvw (tf32-rounded)
    small_gemm<1><<<sg, 256>>>(Wq_r, Wk_r, 0);            // g_M   (tf32-rounded)
    small_gemm<0><<<sg, 256>>>(Wo, Wv_r, 1);              // g_Wov (tf32-rounded)

    // Write attention -> mhat (g_bufA, tf32-rounded)
    write_attn_kernel<<<BB, 256>>>(hidden, mask);

    // vmix = mhat @ Wvw^T -> g_bufB   [32768, 512]
    {
        dim3 grid(MW / TM, DD / TN);
        gemm_tf32<<<grid, 128>>>(/*a*/0, /*w*/0, /*c*/0, MW);
    }

    // wsu = LN(ws + vmix), in-place g_bufB (tf32-rounded)
    ln_ws_kernel<<<MW, 256>>>(workspace, g_ws_p, b_ws_p);

    // [z | wsup] = wsu @ [M | Wov]^T -> g_bufA | g_bufK  [32768, 1024]
    {
        dim3 grid(MW / TM, (2 * DD) / TN);
        gemm_tf32<<<grid, 128>>>(/*a*/1, /*w*/1, /*c*/1, MW);
    }

    // Read attention + final LN -> out
    read_attn_ln_kernel<<<BB, 256>>>(hidden, g_out_p, b_out_p, out);
}

// round 13
// speedup vs baseline: 1.5810x; 1.1110x over previous
#include <cuda_runtime.h>
#include <math.h>
#include <stdint.h>

// Problem constants
#define BB 8192
#define KK 8
#define SS 4
#define DD 512
#define MW (BB * SS)                     // 32768 rows of workspace-space
#define SCALE_F 0.044194173824159216f    // 512^-0.5
#define LN_EPS 1e-5f
#define NEG_INF (__int_as_float(0xff800000))

// ---------------------------------------------------------------------------
// Scratch (device globals). NEVER passed as host-side kernel arguments —
// device code resolves them via selectors (host shadow symbols on GB300 ATS
// silently alias host memory).
// ---------------------------------------------------------------------------
__device__ float g_bufA[(size_t)MW * DD];        // mhat, then z
__device__ float g_bufB[(size_t)MW * DD];        // vmix, then wsu
__device__ float g_bufK[(size_t)MW * DD];        // wsup (projected wsu)
__device__ float g_Aw[SS * DD];                  // Wk_w^T Qws   [S,D]
__device__ float g_M[DD * DD];                   // Wq_r^T Wk_r  [D,D] (tf32-rounded)
__device__ float g_Wov[DD * DD];                 // Wo Wv_r      [D,D] (tf32-rounded)
__device__ float g_Wvw[DD * DD];                 // Wv_w          (tf32-rounded copy)

// ---------------------------------------------------------------------------
// Helpers
// ---------------------------------------------------------------------------
__device__ __forceinline__ float warp_sum(float v) {
    #pragma unroll
    for (int o = 16; o; o >>= 1) v += __shfl_xor_sync(0xffffffffu, v, o);
    return v;
}

__device__ __forceinline__ float warp_dot512(const float* __restrict__ a,
                                             const float* __restrict__ b) {
    int lane = threadIdx.x & 31;
    const float4* a4 = reinterpret_cast<const float4*>(a);
    const float4* b4 = reinterpret_cast<const float4*>(b);
    float s = 0.f;
    #pragma unroll
    for (int i = 0; i < 4; i++) {
        float4 x = a4[lane + i * 32];
        float4 y = b4[lane + i * 32];
        s = fmaf(x.x, y.x, s);
        s = fmaf(x.y, y.y, s);
        s = fmaf(x.z, y.z, s);
        s = fmaf(x.w, y.w, s);
    }
    return warp_sum(s);
}

// round-to-nearest tf32, returned as float bit-pattern
__device__ __forceinline__ float rtf32(float f) {
    uint32_t r;
    asm("cvt.rna.tf32.f32 %0, %1;" : "=r"(r) : "f"(f));
    return __uint_as_float(r);
}

__device__ __forceinline__ void mma_tf32(float* c, const uint32_t* a,
                                         const uint32_t* b) {
    asm volatile(
        "mma.sync.aligned.m16n8k8.row.col.f32.tf32.tf32.f32 "
        "{%0,%1,%2,%3}, {%4,%5,%6,%7}, {%8,%9}, {%0,%1,%2,%3};\n"
        : "+f"(c[0]), "+f"(c[1]), "+f"(c[2]), "+f"(c[3])
        : "r"(a[0]), "r"(a[1]), "r"(a[2]), "r"(a[3]), "r"(b[0]), "r"(b[1]));
}

__device__ __forceinline__ void cp16(void* smem_dst, const void* gsrc) {
    uint32_t s = (uint32_t)__cvta_generic_to_shared(smem_dst);
    asm volatile("cp.async.cg.shared.global [%0], [%1], 16;\n"
                 :: "r"(s), "l"(gsrc));
}

// ---------------------------------------------------------------------------
// Unified precompute: ONE launch, 772 blocks x 256 threads.
//   blocks [0,256):   g_M   = Wq_r^T Wk_r   (32x32 tile per block, tf32 store)
//   blocks [256,512): g_Wov = Wo Wv_r       (same)
//   blocks [512,516): g_Aw  (one block per slot s)
//   blocks [516,772): g_Wvw = rtf32(Wv_w)
// ---------------------------------------------------------------------------
__global__ __launch_bounds__(256) void precompute_kernel(
    const float* __restrict__ ws,
    const float* __restrict__ Wq_w, const float* __restrict__ Wk_w,
    const float* __restrict__ Wv_w,
    const float* __restrict__ Wq_r, const float* __restrict__ Wk_r,
    const float* __restrict__ Wv_r, const float* __restrict__ Wo) {
    const int bid = blockIdx.x;
    const int tid = threadIdx.x;

    __shared__ float As[32][33];
    __shared__ float Bs[32][33];
    __shared__ float qs[DD];

    if (bid < 512) {
        // ---- small GEMM: C = opA(A)*B ----
        const int transA = (bid < 256) ? 1 : 0;
        const float* A = (bid < 256) ? Wq_r : Wo;
        const float* B = (bid < 256) ? Wk_r : Wv_r;
        float* C = (bid < 256) ? g_M : g_Wov;
        const int local = bid & 255;
        const int n0 = (local & 15) * 32;
        const int m0 = (local >> 4) * 32;
        const int tr = tid >> 4;
        const int tc = tid & 15;

        float c00 = 0.f, c01 = 0.f, c10 = 0.f, c11 = 0.f;

        for (int e0 = 0; e0 < DD; e0 += 32) {
            #pragma unroll
            for (int i = tid; i < 1024; i += 256) {
                if (transA) {
                    int e = i >> 5, m = i & 31;
                    As[e][m] = A[(size_t)(e0 + e) * DD + m0 + m];
                } else {
                    int m = i >> 5, e = i & 31;
                    As[e][m] = A[(size_t)(m0 + m) * DD + e0 + e];
                }
            }
            #pragma unroll
            for (int i = tid; i < 1024; i += 256) {
                int e = i >> 5, n = i & 31;
                Bs[e][n] = B[(size_t)(e0 + e) * DD + n0 + n];
            }
            __syncthreads();
            #pragma unroll
            for (int e = 0; e < 32; e++) {
                float a0 = As[e][tr * 2], a1 = As[e][tr * 2 + 1];
                float b0 = Bs[e][tc * 2], b1 = Bs[e][tc * 2 + 1];
                c00 = fmaf(a0, b0, c00);
                c01 = fmaf(a0, b1, c01);
                c10 = fmaf(a1, b0, c10);
                c11 = fmaf(a1, b1, c11);
            }
            __syncthreads();
        }
        C[(size_t)(m0 + tr * 2) * DD + n0 + tc * 2] = rtf32(c00);
        C[(size_t)(m0 + tr * 2) * DD + n0 + tc * 2 + 1] = rtf32(c01);
        C[(size_t)(m0 + tr * 2 + 1) * DD + n0 + tc * 2] = rtf32(c10);
        C[(size_t)(m0 + tr * 2 + 1) * DD + n0 + tc * 2 + 1] = rtf32(c11);
    } else if (bid < 516) {
        // ---- Aw[s,:] for slot s = bid-512 ----
        const int s = bid - 512;
        const int warp = tid >> 5;

        for (int e = warp; e < DD; e += 8) {
            float d = warp_dot512(ws + s * DD, Wq_w + (size_t)e * DD);
            if ((tid & 31) == 0) qs[e] = d;
        }
        __syncthreads();

        #pragma unroll
        for (int h = 0; h < 2; h++) {
            int d = tid + h * 256;
            float acc = 0.f;
            for (int e = 0; e < DD; e++)
                acc = fmaf(qs[e], Wk_w[(size_t)e * DD + d], acc);
            g_Aw[s * DD + d] = acc;
        }
    } else {
        // ---- tf32-rounded copy of Wv_w ----
        size_t i = ((size_t)(bid - 516) * 256 + tid) * 4;
        float4 v = *reinterpret_cast<const float4*>(Wv_w + i);
        float4 o;
        o.x = rtf32(v.x); o.y = rtf32(v.y); o.z = rtf32(v.z); o.w = rtf32(v.w);
        *reinterpret_cast<float4*>(g_Wvw + i) = o;
    }
}

// ---------------------------------------------------------------------------
// tf32 tensor-core GEMM (NT): C[M,*] = A[M,512] @ W[n,:]^T
// 128x128 block tile, 4 warps of 64x64, TKS=16.
// 3-buffer swizzled smem (48KB total), ONE syncthreads + ONE wait per k-tile.
// Swizzle: physical 4-word chunk = logical chunk XOR ((row>>1)&3) —
// conflict-free fragment reads at stride 16.
// Inputs are ALREADY tf32-rounded (producers round).
//   a_sel: 0=g_bufA 1=g_bufB
//   wmode: 0=g_Wvw(N=512)  1=cols[0,512)->g_M, [512,1024)->g_Wov
//   cmode: 0=g_bufB        1=cols[0,512)->g_bufA, [512,1024)->g_bufK
// ---------------------------------------------------------------------------
#define TM 128
#define TN 128
#define TKS 16
#define NTILE (DD / TKS)                 // 32

__global__ __launch_bounds__(128) void gemm_tf32(
    int a_sel, int wmode, int cmode, int M) {
    const float* A = (a_sel == 0) ? g_bufA : g_bufB;
    const int bm = blockIdx.x * TM;
    const int bn = blockIdx.y * TN;

    const float* W;
    int wn0;
    if (wmode == 0) { W = g_Wvw; wn0 = bn; }
    else { W = (bn < 512) ? g_M : g_Wov; wn0 = bn & 511; }

    float* C;
    int cn0;
    if (cmode == 0) { C = g_bufB; cn0 = bn; }
    else { C = (bn < 512) ? g_bufA : g_bufK; cn0 = bn & 511; }

    __shared__ uint32_t As[3][TM][16];   // 24 KB
    __shared__ uint32_t Bs[3][TN][16];   // 24 KB  (total 48 KB exactly)

    const int tid = threadIdx.x;
    const int lane = tid & 31;
    const int warp = tid >> 5;
    const int wm = warp & 1;          // 2 warps along M (64 rows each)
    const int wn = warp >> 1;         // 2 warps along N (64 cols each)
    const int gid = lane >> 2;
    const int tig = lane & 3;

    // cp.async mapping: thread covers 4 A-rows and 4 B-rows, one 16B chunk each
    const int cr = tid >> 2;          // 0..31 (+32i)
    const int ch = tid & 3;           // logical chunk 0..3
    const float* arow = A + (size_t)(bm + cr) * DD + ch * 4;
    const float* wrow = W + (size_t)(wn0 + cr) * DD + ch * 4;

    float acc[4][8][4];
    #pragma unroll
    for (int i = 0; i < 4; i++)
        #pragma unroll
        for (int j = 0; j < 8; j++)
            #pragma unroll
            for (int r = 0; r < 4; r++) acc[i][j][r] = 0.f;

    // prologue: issue stages 0 and 1
    #pragma unroll
    for (int s = 0; s < 2; s++) {
        int k0 = s * TKS;
        #pragma unroll
        for (int i = 0; i < 4; i++) {
            int r = cr + i * 32;
            int pc = (ch ^ ((r >> 1) & 3)) * 4;
            cp16(&As[s][r][pc], arow + (size_t)i * 32 * DD + k0);
            cp16(&Bs[s][r][pc], wrow + (size_t)i * 32 * DD + k0);
        }
        asm volatile("cp.async.commit_group;\n" ::: "memory");
    }

    for (int t = 0; t < NTILE; t++) {
        if (t == NTILE - 1)
            asm volatile("cp.async.wait_group 0;\n" ::: "memory");
        else
            asm volatile("cp.async.wait_group 1;\n" ::: "memory");
        __syncthreads();   // stage t visible to all; all readers past buf (t-1)

        // issue stage t+2 into buffer (t+2)%3 == (t-1)%3 (retired by the sync)
        if (t + 2 < NTILE) {
            int sb = (t + 2) % 3;
            int k0 = (t + 2) * TKS;
            #pragma unroll
            for (int i = 0; i < 4; i++) {
                int r = cr + i * 32;
                int pc = (ch ^ ((r >> 1) & 3)) * 4;
                cp16(&As[sb][r][pc], arow + (size_t)i * 32 * DD + k0);
                cp16(&Bs[sb][r][pc], wrow + (size_t)i * 32 * DD + k0);
            }
            asm volatile("cp.async.commit_group;\n" ::: "memory");
        }

        const int buf = t % 3;
        #pragma unroll
        for (int ks = 0; ks < 2; ks++) {
            uint32_t af[4][4], bf[8][2];
            #pragma unroll
            for (int mt = 0; mt < 4; mt++) {
                int r0 = wm * 64 + mt * 16 + gid;     // (r0>>1)&3 == ((r0+8)>>1)&3
                int x = (r0 >> 1) & 3;
                int p0 = (((2 * ks) ^ x) << 2) | tig;
                int p1 = (((2 * ks + 1) ^ x) << 2) | tig;
                af[mt][0] = As[buf][r0][p0];
                af[mt][1] = As[buf][r0 + 8][p0];
                af[mt][2] = As[buf][r0][p1];
                af[mt][3] = As[buf][r0 + 8][p1];
            }
            #pragma unroll
            for (int nt = 0; nt < 8; nt++) {
                int c0 = wn * 64 + nt * 8 + gid;
                int x = (c0 >> 1) & 3;
                int p0 = (((2 * ks) ^ x) << 2) | tig;
                int p1 = (((2 * ks + 1) ^ x) << 2) | tig;
                bf[nt][0] = Bs[buf][c0][p0];
                bf[nt][1] = Bs[buf][c0][p1];
            }
            #pragma unroll
            for (int mt = 0; mt < 4; mt++)
                #pragma unroll
                for (int nt = 0; nt < 8; nt++)
                    mma_tf32(acc[mt][nt], af[mt], bf[nt]);
        }
    }

    #pragma unroll
    for (int mt = 0; mt < 4; mt++) {
        #pragma unroll
        for (int nt = 0; nt < 8; nt++) {
            int grow = bm + wm * 64 + mt * 16 + gid;
            int gcol = cn0 + wn * 64 + nt * 8 + 2 * tig;
            *reinterpret_cast<float2*>(&C[(size_t)grow * DD + gcol]) =
                make_float2(acc[mt][nt][0], acc[mt][nt][1]);
            *reinterpret_cast<float2*>(&C[(size_t)(grow + 8) * DD + gcol]) =
                make_float2(acc[mt][nt][2], acc[mt][nt][3]);
        }
    }
}

// ---------------------------------------------------------------------------
// Write attention -> mhat (g_bufA, tf32-rounded). One block per batch b.
// ---------------------------------------------------------------------------
__global__ __launch_bounds__(256) void write_attn_kernel(
    const float* __restrict__ hidden,
    const int* __restrict__ mask) {
    const int b = blockIdx.x;
    const int tid = threadIdx.x;
    const int warp = tid >> 5;

    __shared__ float sh[KK][DD];
    __shared__ float logits[SS][KK];
    __shared__ float p[SS][KK];
    __shared__ int smask[KK];

    if (tid < KK) smask[tid] = mask[b * KK + tid];

    for (int i = tid; i < KK * (DD / 4); i += 256) {
        int k = i / (DD / 4), c4 = i % (DD / 4);
        reinterpret_cast<float4*>(sh[k])[c4] =
            reinterpret_cast<const float4*>(hidden + (size_t)(b * KK + k) * DD)[c4];
    }
    __syncthreads();

    for (int pr = warp; pr < SS * KK; pr += 8) {
        int s = pr >> 3, k = pr & 7;
        float d = warp_dot512(g_Aw + s * DD, sh[k]) * SCALE_F;
        if ((tid & 31) == 0) logits[s][k] = d;
    }
    __syncthreads();

    if (tid < SS) {
        int s = tid;
        float m = NEG_INF;
        #pragma unroll
        for (int k = 0; k < KK; k++)
            if (smask[k] != 0) m = fmaxf(m, logits[s][k]);
        float pe[KK], sum = 0.f;
        #pragma unroll
        for (int k = 0; k < KK; k++) {
            float e = (smask[k] != 0) ? expf(logits[s][k] - m) : 0.f;
            pe[k] = e; sum += e;
        }
        float inv = (sum > 0.f) ? 1.f / sum : 0.f;
        #pragma unroll
        for (int k = 0; k < KK; k++) p[s][k] = pe[k] * inv;
    }
    __syncthreads();

    #pragma unroll
    for (int s = 0; s < SS; s++) {
        #pragma unroll
        for (int h = 0; h < 2; h++) {
            int d = tid + h * 256;
            float acc = 0.f;
            #pragma unroll
            for (int k = 0; k < KK; k++) acc = fmaf(p[s][k], sh[k][d], acc);
            g_bufA[(size_t)(b * SS + s) * DD + d] = rtf32(acc);
        }
    }
}

// ---------------------------------------------------------------------------
// wsu = LN(ws[s] + vmix) in-place on g_bufB (tf32-rounded store).
// ---------------------------------------------------------------------------
__global__ __launch_bounds__(256) void ln_ws_kernel(
    const float* __restrict__ workspace,
    const float* __restrict__ g, const float* __restrict__ bb) {
    const size_t row = blockIdx.x;
    const int s = (int)(row & (SS - 1));
    const int tid = threadIdx.x;
    const int warp = tid >> 5;
    __shared__ float s_part[2][8];
    __shared__ float s_stats[2];

    float vv[2];
    #pragma unroll
    for (int h = 0; h < 2; h++) {
        int d = tid + h * 256;
        vv[h] = workspace[s * DD + d] + g_bufB[row * DD + d];
    }
    float sum = warp_sum(vv[0] + vv[1]);
    float sq = warp_sum(vv[0] * vv[0] + vv[1] * vv[1]);
    if ((tid & 31) == 0) { s_part[0][warp] = sum; s_part[1][warp] = sq; }
    __syncthreads();
    if (tid == 0) {
        float ts = 0.f, tq = 0.f;
        #pragma unroll
        for (int w = 0; w < 8; w++) { ts += s_part[0][w]; tq += s_part[1][w]; }
        float mu = ts * (1.f / DD);
        float var = tq * (1.f / DD) - mu * mu;
        s_stats[0] = mu; s_stats[1] = rsqrtf(var + LN_EPS);
    }
    __syncthreads();
    float mu = s_stats[0], ri = s_stats[1];
    #pragma unroll
    for (int h = 0; h < 2; h++) {
        int d = tid + h * 256;
        g_bufB[row * DD + d] = rtf32((vv[h] - mu) * ri * g[d] + bb[d]);
    }
}

// ---------------------------------------------------------------------------
// Read attention + FINAL LN fused. One block per batch b.
// ---------------------------------------------------------------------------
__global__ __launch_bounds__(256) void read_attn_ln_kernel(
    const float* __restrict__ hidden,
    const float* __restrict__ gam, const float* __restrict__ bet,
    float* __restrict__ out) {
    const int b = blockIdx.x;
    const int tid = threadIdx.x;
    const int lane = tid & 31;
    const int warp = tid >> 5;

    __shared__ float sh[KK][DD];
    __shared__ float sz[SS][DD];
    __shared__ float sw[SS][DD];
    __shared__ float logits[KK][SS];
    __shared__ float p[KK][SS];

    for (int i = tid; i < KK * (DD / 4); i += 256) {
        int k = i / (DD / 4), c4 = i % (DD / 4);
        reinterpret_cast<float4*>(sh[k])[c4] =
            reinterpret_cast<const float4*>(hidden + (size_t)(b * KK + k) * DD)[c4];
    }
    for (int i = tid; i < SS * (DD / 4); i += 256) {
        int s = i / (DD / 4), c4 = i % (DD / 4);
        reinterpret_cast<float4*>(sz[s])[c4] =
            reinterpret_cast<const float4*>(g_bufA + (size_t)(b * SS + s) * DD)[c4];
        reinterpret_cast<float4*>(sw[s])[c4] =
            reinterpret_cast<const float4*>(g_bufK + (size_t)(b * SS + s) * DD)[c4];
    }
    __syncthreads();

    for (int pr = warp; pr < KK * SS; pr += 8) {
        int k = pr >> 2, s = pr & 3;
        float d = warp_dot512(sh[k], sz[s]) * SCALE_F;
        if (lane == 0) logits[k][s] = d;
    }
    __syncthreads();

    if (tid < KK) {
        int k = tid;
        float m = NEG_INF;
        #pragma unroll
        for (int s = 0; s < SS; s++) m = fmaxf(m, logits[k][s]);
        float pe[SS], sum = 0.f;
        #pragma unroll
        for (int s = 0; s < SS; s++) { pe[s] = expf(logits[k][s] - m); sum += pe[s]; }
        float inv = 1.f / sum;
        #pragma unroll
        for (int s = 0; s < SS; s++) p[k][s] = pe[s] * inv;
    }
    __syncthreads();

    {
        const int k = warp;
        float pv[SS];
        #pragma unroll
        for (int s = 0; s < SS; s++) pv[s] = p[k][s];

        float vals[16];
        float lsum = 0.f, lsq = 0.f;
        #pragma unroll
        for (int j = 0; j < 16; j++) {
            int d = lane + j * 32;
            float a = 0.f;
            #pragma unroll
            for (int s = 0; s < SS; s++) a = fmaf(pv[s], sw[s][d], a);
            float x = sh[k][d] + a;
            vals[j] = x;
            lsum += x;
            lsq = fmaf(x, x, lsq);
        }
        lsum = warp_sum(lsum);
        lsq = warp_sum(lsq);
        float mu = lsum * (1.f / DD);
        float var = lsq * (1.f / DD) - mu * mu;
        float ri = rsqrtf(var + LN_EPS);

        float* orow = out + (size_t)(b * KK + k) * DD;
        #pragma unroll
        for (int j = 0; j < 16; j++) {
            int d = lane + j * 32;
            orow[d] = fmaf((vals[j] - mu) * ri, __ldg(&gam[d]), __ldg(&bet[d]));
        }
    }
}

// ---------------------------------------------------------------------------
// Launch — kernel launches ONLY; only harness pointers cross the boundary.
// ---------------------------------------------------------------------------
extern "C" void kernel_launch(void* const* d_in, const int* in_sizes, int n_in,
                              void* d_out, int out_size) {
    const float* hidden = (const float*)d_in[0];
    const int* mask = (const int*)d_in[1];
    const float* workspace = (const float*)d_in[2];
    const float* Wq_w = (const float*)d_in[3];
    const float* Wk_w = (const float*)d_in[4];
    const float* Wv_w = (const float*)d_in[5];
    const float* Wq_r = (const float*)d_in[6];
    const float* Wk_r = (const float*)d_in[7];
    const float* Wv_r = (const float*)d_in[8];
    const float* Wo = (const float*)d_in[9];
    const float* g_ws_p = (const float*)d_in[10];
    const float* b_ws_p = (const float*)d_in[11];
    const float* g_out_p = (const float*)d_in[12];
    const float* b_out_p = (const float*)d_in[13];
    float* out = (float*)d_out;

    // ALL batch-independent precomputes in one launch (772 blocks)
    precompute_kernel<<<772, 256>>>(workspace, Wq_w, Wk_w, Wv_w,
                                    Wq_r, Wk_r, Wv_r, Wo);

    // Write attention -> mhat (g_bufA, tf32-rounded)
    write_attn_kernel<<<BB, 256>>>(hidden, mask);

    // vmix = mhat @ Wvw^T -> g_bufB   [32768, 512]
    {
        dim3 grid(MW / TM, DD / TN);
        gemm_tf32<<<grid, 128>>>(/*a*/0, /*w*/0, /*c*/0, MW);
    }

    // wsu = LN(ws + vmix), in-place g_bufB (tf32-rounded)
    ln_ws_kernel<<<MW, 256>>>(workspace, g_ws_p, b_ws_p);

    // [z | wsup] = wsu @ [M | Wov]^T -> g_bufA | g_bufK  [32768, 1024]
    {
        dim3 grid(MW / TM, (2 * DD) / TN);
        gemm_tf32<<<grid, 128>>>(/*a*/1, /*w*/1, /*c*/1, MW);
    }

    // Read attention + final LN -> out
    read_attn_ln_kernel<<<BB, 256>>>(hidden, g_out_p, b_out_p, out);
}